// round 15
// baseline (speedup 1.0000x reference)
#include <cuda_runtime.h>
#include <cuda_bf16.h>
#include <mma.h>
#include <math.h>
#include <stdint.h>

using namespace nvcuda;
typedef __nv_bfloat16 bf16;

// Problem constants
#define BQ   8
#define SEQ  1024
#define CH   512
#define HIDC 2048
#define NHD  8
#define HDIM 64
#define ROWS (BQ*SEQ)          // 8192
#define QKVW (3*CH)            // 1536

// ---------------- scratch ----------------------------------------------------
__device__ bf16  g_wqkv[QKVW*CH];
__device__ bf16  g_wproj[CH*CH];
__device__ bf16  g_wfc1[HIDC*CH];
__device__ bf16  g_wfc2[CH*HIDC];
__device__ bf16  g_ln16[ROWS*CH];
__device__ bf16  g_qkv16[(size_t)ROWS*QKVW];
__device__ bf16  g_at16[ROWS*CH];
__device__ float g_x1 [ROWS*CH];
__device__ bf16  g_h16 [(size_t)ROWS*HIDC];
__device__ bf16  g_h216[(size_t)ROWS*HIDC];

// ---------------- helpers ---------------------------------------------------
__device__ __forceinline__ uint32_t su32(const void* p) {
    uint32_t a;
    asm("{ .reg .u64 t; cvta.to.shared.u64 t, %1; cvt.u32.u64 %0, t; }"
        : "=r"(a) : "l"(p));
    return a;
}
#define CPA16(d, s) asm volatile("cp.async.cg.shared.global [%0], [%1], 16;" :: "r"(d), "l"(s))
#define CPCOMMIT()  asm volatile("cp.async.commit_group;" ::: "memory")
#define CPWAIT(n)   asm volatile("cp.async.wait_group %0;" :: "n"(n) : "memory")

__device__ __forceinline__ void mma_bf16(float c[4],
    uint32_t a0, uint32_t a1, uint32_t a2, uint32_t a3,
    uint32_t b0, uint32_t b1)
{
    asm volatile(
        "mma.sync.aligned.m16n8k16.row.col.f32.bf16.bf16.f32 "
        "{%0,%1,%2,%3}, {%4,%5,%6,%7}, {%8,%9}, {%0,%1,%2,%3};"
        : "+f"(c[0]), "+f"(c[1]), "+f"(c[2]), "+f"(c[3])
        : "r"(a0), "r"(a1), "r"(a2), "r"(a3), "r"(b0), "r"(b1));
}
__device__ __forceinline__ void ldsm4t(uint32_t r[4], uint32_t addr) {
    asm volatile("ldmatrix.sync.aligned.m8n8.x4.trans.shared.b16 {%0,%1,%2,%3}, [%4];"
                 : "=r"(r[0]), "=r"(r[1]), "=r"(r[2]), "=r"(r[3]) : "r"(addr));
}
__device__ __forceinline__ uint32_t packbf(float lo, float hi) {
    uint32_t r;
    asm("cvt.rn.bf16x2.f32 %0, %1, %2;" : "=r"(r) : "f"(hi), "f"(lo));
    return r;
}

// ---------------- fused fp32 -> bf16 weight conversion ----------------------
// segment sizes (elements): qkv 786432, proj 262144, fc1 1048576, fc2 1048576
#define CVT_S0 786432
#define CVT_S1 (CVT_S0 + 262144)     // 1048576
#define CVT_S2 (CVT_S1 + 1048576)    // 2097152
#define CVT_TOT (CVT_S2 + 1048576)   // 3145728
__global__ void to_bf16_all(const float* __restrict__ w0, bf16* __restrict__ d0,
                            const float* __restrict__ w1, bf16* __restrict__ d1,
                            const float* __restrict__ w2, bf16* __restrict__ d2,
                            const float* __restrict__ w3, bf16* __restrict__ d3)
{
    size_t i = ((size_t)blockIdx.x * 256 + threadIdx.x) * 4;
    const float* s; bf16* d; size_t off;
    if (i < CVT_S0)      { s = w0; d = d0; off = i; }
    else if (i < CVT_S1) { s = w1; d = d1; off = i - CVT_S0; }
    else if (i < CVT_S2) { s = w2; d = d2; off = i - CVT_S1; }
    else                 { s = w3; d = d3; off = i - CVT_S2; }
    float4 v = *(const float4*)(s + off);
    bf16 t[4] = { __float2bfloat16(v.x), __float2bfloat16(v.y),
                  __float2bfloat16(v.z), __float2bfloat16(v.w) };
    *(uint2*)(d + off) = *(uint2*)t;
}

// ---------------- LayerNorm (fp32 in, bf16 out) -----------------------------
__global__ void ln_kernel(const float* __restrict__ x,
                          const float* __restrict__ g,
                          const float* __restrict__ b,
                          bf16* __restrict__ out)
{
    int row = blockIdx.x;
    const float* xr = x + (size_t)row * CH;
    bf16* orow = out + (size_t)row * CH;
    int t = threadIdx.x;
    float v[4];
    float s = 0.f;
#pragma unroll
    for (int i = 0; i < 4; i++) { v[i] = xr[t + i*128]; s += v[i]; }
    __shared__ float red[4];
#pragma unroll
    for (int o = 16; o > 0; o >>= 1) s += __shfl_xor_sync(0xffffffffu, s, o);
    if ((t & 31) == 0) red[t >> 5] = s;
    __syncthreads();
    float mean = (red[0] + red[1] + red[2] + red[3]) * (1.0f / CH);
    float vs = 0.f;
#pragma unroll
    for (int i = 0; i < 4; i++) { float d = v[i] - mean; vs += d * d; }
#pragma unroll
    for (int o = 16; o > 0; o >>= 1) vs += __shfl_xor_sync(0xffffffffu, vs, o);
    __syncthreads();
    if ((t & 31) == 0) red[t >> 5] = vs;
    __syncthreads();
    float var = (red[0] + red[1] + red[2] + red[3]) * (1.0f / CH);
    float rstd = rsqrtf(var + 1e-5f);
#pragma unroll
    for (int i = 0; i < 4; i++) {
        int c = t + i*128;
        orow[c] = __float2bfloat16((v[i] - mean) * rstd * g[c] + b[c]);
    }
}

// ---------------- bf16 WMMA GEMM, 2-stage cp.async (R13 proven) -------------
#define LDSB 72                 // bf16 elems per smem row (144B)
#define TILE_E (128*LDSB)
#define GT_SMEM (4*TILE_E*2)    // 73728

template<typename OutT>
__global__ __launch_bounds__(256, 2)
void gemm_bf(const bf16* __restrict__ A, int lda,
             const bf16* __restrict__ B, int ldb,
             const float* __restrict__ bias,
             const float* __restrict__ res, int ldres,
             OutT* __restrict__ out, int ldo, int K)
{
    extern __shared__ char dsmc[];
    bf16* As = (bf16*)dsmc;
    bf16* Bs = As + 2*TILE_E;

    int tid = threadIdx.x;
    int wid = tid >> 5;
    int wm = wid >> 2;
    int wn = wid & 3;
    int m0 = blockIdx.y * 128;
    int n0 = blockIdx.x * 128;

    wmma::fragment<wmma::accumulator, 16, 16, 16, float> fc[4][2];
#pragma unroll
    for (int i = 0; i < 4; i++)
#pragma unroll
        for (int j = 0; j < 2; j++)
            wmma::fill_fragment(fc[i][j], 0.0f);

    int lrow  = tid >> 1;
    int sbase = (tid & 1) * 4;

    int nK = K / 64;

#pragma unroll
    for (int j = 0; j < 4; j++) {
        int cseg = (sbase + j) * 8;
        CPA16(su32(&As[lrow * LDSB + cseg]), A + (size_t)(m0 + lrow) * lda + cseg);
        CPA16(su32(&Bs[lrow * LDSB + cseg]), B + (size_t)(n0 + lrow) * ldb + cseg);
    }
    CPCOMMIT();

    for (int kc = 0; kc < nK; kc++) {
        int cur = kc & 1;
        if (kc + 1 < nK) {
            int nxt = cur ^ 1;
            int k0 = (kc + 1) * 64;
#pragma unroll
            for (int j = 0; j < 4; j++) {
                int cseg = (sbase + j) * 8;
                CPA16(su32(&As[nxt * TILE_E + lrow * LDSB + cseg]),
                      A + (size_t)(m0 + lrow) * lda + k0 + cseg);
                CPA16(su32(&Bs[nxt * TILE_E + lrow * LDSB + cseg]),
                      B + (size_t)(n0 + lrow) * ldb + k0 + cseg);
            }
            CPCOMMIT();
            CPWAIT(1);
        } else {
            CPWAIT(0);
        }
        __syncthreads();

        bf16* Ac = As + cur * TILE_E;
        bf16* Bc = Bs + cur * TILE_E;
#pragma unroll
        for (int ks = 0; ks < 4; ks++) {
            wmma::fragment<wmma::matrix_a, 16, 16, 16, bf16, wmma::row_major> fa[4];
            wmma::fragment<wmma::matrix_b, 16, 16, 16, bf16, wmma::col_major> fb[2];
#pragma unroll
            for (int i = 0; i < 4; i++)
                wmma::load_matrix_sync(fa[i], &Ac[(wm * 64 + i * 16) * LDSB + ks * 16], LDSB);
#pragma unroll
            for (int j = 0; j < 2; j++)
                wmma::load_matrix_sync(fb[j], &Bc[(wn * 32 + j * 16) * LDSB + ks * 16], LDSB);
#pragma unroll
            for (int i = 0; i < 4; i++)
#pragma unroll
                for (int j = 0; j < 2; j++)
                    wmma::mma_sync(fc[i][j], fa[i], fb[j], fc[i][j]);
        }
        __syncthreads();
    }

    float* eps = (float*)dsmc;
#pragma unroll
    for (int i = 0; i < 4; i++)
#pragma unroll
        for (int j = 0; j < 2; j++)
            wmma::store_matrix_sync(&eps[(wm * 64 + i * 16) * 132 + wn * 32 + j * 16],
                                    fc[i][j], 132, wmma::mem_row_major);
    __syncthreads();

    int r = tid >> 1;
    int c0 = (tid & 1) * 64;
#pragma unroll
    for (int c = 0; c < 64; c += 4) {
        float4 v = *(float4*)&eps[r * 132 + c0 + c];
        int n = n0 + c0 + c;
        if (bias) {
            v.x += bias[n]; v.y += bias[n + 1]; v.z += bias[n + 2]; v.w += bias[n + 3];
        }
        if (res) {
            float4 rr = *(const float4*)(res + (size_t)(m0 + r) * ldres + n);
            v.x += rr.x; v.y += rr.y; v.z += rr.z; v.w += rr.w;
        }
        if constexpr (sizeof(OutT) == 4) {
            *(float4*)((float*)out + (size_t)(m0 + r) * ldo + n) = v;
        } else {
            bf16 t[4] = { __float2bfloat16(v.x), __float2bfloat16(v.y),
                          __float2bfloat16(v.z), __float2bfloat16(v.w) };
            *(uint2*)((bf16*)out + (size_t)(m0 + r) * ldo + n) = *(uint2*)t;
        }
    }
}

// ---------------- Flash attention: register-resident mma.sync ---------------
// CTA: 64 queries x one head; 128 threads (4 warps), warp = 16 query rows.
__global__ __launch_bounds__(128, 3)
void flash_reg(const bf16* __restrict__ qkv, bf16* __restrict__ out)
{
    __shared__ __align__(16) bf16 Qs[64 * LDSB];
    __shared__ __align__(16) bf16 Kb[2][64 * LDSB];
    __shared__ __align__(16) bf16 Vb[2][64 * LDSB];

    int bz = blockIdx.y;
    int bI = bz / NHD, hI = bz % NHD;
    int q0 = blockIdx.x * 64;
    const bf16* base = qkv + (size_t)bI * SEQ * QKVW + hI * 3 * HDIM;

    int tid = threadIdx.x;
    int wid = tid >> 5;
    int lane = tid & 31;
    int lr = tid >> 1;              // 0..63 (row for loads)
    int lc = (tid & 1) * 32;        // col base for loads

    auto issue_kv = [&](int t0) {
        int buf = (t0 >> 6) & 1;
        const bf16* kp = base + (size_t)(t0 + lr) * QKVW + HDIM + lc;
        const bf16* vp = base + (size_t)(t0 + lr) * QKVW + 2 * HDIM + lc;
#pragma unroll
        for (int j = 0; j < 4; j++) {
            CPA16(su32(&Kb[buf][lr * LDSB + lc + j * 8]), kp + j * 8);
            CPA16(su32(&Vb[buf][lr * LDSB + lc + j * 8]), vp + j * 8);
        }
        CPCOMMIT();
    };

    issue_kv(0);
    // Q -> smem : 32 cols per thread = 4 x uint4 (8 bf16 each)
    {
        const bf16* qp = base + (size_t)(q0 + lr) * QKVW + lc;
#pragma unroll
        for (int j = 0; j < 4; j++)
            *(uint4*)&Qs[lr * LDSB + lc + j * 8] = *(const uint4*)(qp + j * 8);
    }
    __syncthreads();

    // Q A-fragments (row-major m16k16), per warp rows wid*16..+15
    uint32_t qa[4][4];
    {
        int r0 = wid * 16 + (lane >> 2);
        int cb = (lane & 3) * 2;
#pragma unroll
        for (int kb = 0; kb < 4; kb++) {
            const bf16* qb = &Qs[0] + kb * 16 + cb;
            qa[kb][0] = *(const uint32_t*)(qb + (size_t)r0 * LDSB);
            qa[kb][1] = *(const uint32_t*)(qb + (size_t)(r0 + 8) * LDSB);
            qa[kb][2] = *(const uint32_t*)(qb + (size_t)r0 * LDSB + 8);
            qa[kb][3] = *(const uint32_t*)(qb + (size_t)(r0 + 8) * LDSB + 8);
        }
    }

    float oc[8][4];
#pragma unroll
    for (int nt = 0; nt < 8; nt++)
#pragma unroll
        for (int j = 0; j < 4; j++) oc[nt][j] = 0.f;
    float mrow[2] = { -1e30f, -1e30f };
    float lsum[2] = { 0.f, 0.f };

    int krow = lane >> 2;           // b-frag n index
    int kcol = (lane & 3) * 2;      // b-frag k offset
    int lmrow = (lane & 7) + ((lane >> 3) & 1) * 8;
    int lmcol = (lane >> 4) * 8;

    for (int t0 = 0; t0 < SEQ; t0 += 64) {
        CPWAIT(0);
        __syncthreads();
        if (t0 + 64 < SEQ) issue_kv(t0 + 64);

        int buf = (t0 >> 6) & 1;
        const bf16* Ks = Kb[buf];
        const bf16* Vs = Vb[buf];

        // ---- S = Q @ K^T : 8 n-tiles x 4 k-blocks
        float sc[8][4];
#pragma unroll
        for (int nt = 0; nt < 8; nt++)
#pragma unroll
            for (int j = 0; j < 4; j++) sc[nt][j] = 0.f;
#pragma unroll
        for (int kb = 0; kb < 4; kb++) {
#pragma unroll
            for (int nt = 0; nt < 8; nt++) {
                const bf16* kbp = Ks + (size_t)(nt * 8 + krow) * LDSB + kb * 16 + kcol;
                uint32_t b0 = *(const uint32_t*)(kbp);
                uint32_t b1 = *(const uint32_t*)(kbp + 8);
                mma_bf16(sc[nt], qa[kb][0], qa[kb][1], qa[kb][2], qa[kb][3], b0, b1);
            }
        }

        // ---- online softmax in registers
        float mx0 = -1e30f, mx1 = -1e30f;
#pragma unroll
        for (int nt = 0; nt < 8; nt++) {
            mx0 = fmaxf(mx0, fmaxf(sc[nt][0], sc[nt][1]));
            mx1 = fmaxf(mx1, fmaxf(sc[nt][2], sc[nt][3]));
        }
        mx0 *= 0.125f; mx1 *= 0.125f;
        mx0 = fmaxf(mx0, __shfl_xor_sync(0xffffffffu, mx0, 1));
        mx0 = fmaxf(mx0, __shfl_xor_sync(0xffffffffu, mx0, 2));
        mx1 = fmaxf(mx1, __shfl_xor_sync(0xffffffffu, mx1, 1));
        mx1 = fmaxf(mx1, __shfl_xor_sync(0xffffffffu, mx1, 2));

        float mn0 = fmaxf(mrow[0], mx0);
        float mn1 = fmaxf(mrow[1], mx1);
        float sf0 = __expf(mrow[0] - mn0);
        float sf1 = __expf(mrow[1] - mn1);
        mrow[0] = mn0; mrow[1] = mn1;

        float sum0 = 0.f, sum1 = 0.f;
#pragma unroll
        for (int nt = 0; nt < 8; nt++) {
            sc[nt][0] = __expf(sc[nt][0] * 0.125f - mn0);
            sc[nt][1] = __expf(sc[nt][1] * 0.125f - mn0);
            sc[nt][2] = __expf(sc[nt][2] * 0.125f - mn1);
            sc[nt][3] = __expf(sc[nt][3] * 0.125f - mn1);
            sum0 += sc[nt][0] + sc[nt][1];
            sum1 += sc[nt][2] + sc[nt][3];
        }
        sum0 += __shfl_xor_sync(0xffffffffu, sum0, 1);
        sum0 += __shfl_xor_sync(0xffffffffu, sum0, 2);
        sum1 += __shfl_xor_sync(0xffffffffu, sum1, 1);
        sum1 += __shfl_xor_sync(0xffffffffu, sum1, 2);
        lsum[0] = lsum[0] * sf0 + sum0;
        lsum[1] = lsum[1] * sf1 + sum1;

#pragma unroll
        for (int nt = 0; nt < 8; nt++) {
            oc[nt][0] *= sf0; oc[nt][1] *= sf0;
            oc[nt][2] *= sf1; oc[nt][3] *= sf1;
        }

        // ---- pack P into A-fragments
        uint32_t pa[4][4];
#pragma unroll
        for (int kb = 0; kb < 4; kb++) {
            pa[kb][0] = packbf(sc[2*kb][0],   sc[2*kb][1]);
            pa[kb][1] = packbf(sc[2*kb][2],   sc[2*kb][3]);
            pa[kb][2] = packbf(sc[2*kb+1][0], sc[2*kb+1][1]);
            pa[kb][3] = packbf(sc[2*kb+1][2], sc[2*kb+1][3]);
        }

        // ---- O += P @ V : V B-frags via ldmatrix.x4.trans
#pragma unroll
        for (int kb = 0; kb < 4; kb++) {
#pragma unroll
            for (int dg = 0; dg < 4; dg++) {
                uint32_t vr[4];
                uint32_t addr = su32(Vs + (size_t)(kb * 16 + lmrow) * LDSB + dg * 16 + lmcol);
                ldsm4t(vr, addr);
                mma_bf16(oc[2*dg],     pa[kb][0], pa[kb][1], pa[kb][2], pa[kb][3], vr[0], vr[1]);
                mma_bf16(oc[2*dg + 1], pa[kb][0], pa[kb][1], pa[kb][2], pa[kb][3], vr[2], vr[3]);
            }
        }
    }

    // ---- writeout O / l
    {
        float inv0 = 1.0f / lsum[0];
        float inv1 = 1.0f / lsum[1];
        int r0 = wid * 16 + (lane >> 2);
        int cb = (lane & 3) * 2;
        bf16* op0 = out + ((size_t)bI * SEQ + q0 + r0) * CH + hI * HDIM + cb;
        bf16* op1 = op0 + (size_t)8 * CH;
#pragma unroll
        for (int nt = 0; nt < 8; nt++) {
            *(uint32_t*)(op0 + nt * 8) = packbf(oc[nt][0] * inv0, oc[nt][1] * inv0);
            *(uint32_t*)(op1 + nt * 8) = packbf(oc[nt][2] * inv1, oc[nt][3] * inv1);
        }
    }
}

// ---------------- Depthwise 3x3 conv + exact GELU, 8 channels/thread --------
__global__ __launch_bounds__(256)
void dwgelu_kernel(const bf16* __restrict__ h,
                   const float* __restrict__ w,
                   const float* __restrict__ bias,
                   bf16* __restrict__ out)
{
    int n = blockIdx.y;
    int b = blockIdx.z;
    int c = threadIdx.x * 8;        // 256 threads x 8 = 2048 channels
    int hh = n >> 5, ww = n & 31;

    float acc[8];
    {
        float4 b0 = *(const float4*)(bias + c);
        float4 b1 = *(const float4*)(bias + c + 4);
        acc[0] = b0.x; acc[1] = b0.y; acc[2] = b0.z; acc[3] = b0.w;
        acc[4] = b1.x; acc[5] = b1.y; acc[6] = b1.z; acc[7] = b1.w;
    }

#pragma unroll
    for (int dy = -1; dy <= 1; dy++) {
        int y = hh + dy;
        if (y < 0 || y >= 32) continue;
#pragma unroll
        for (int dx = -1; dx <= 1; dx++) {
            int xw = ww + dx;
            if (xw < 0 || xw >= 32) continue;
            uint4 hv = *(const uint4*)(h + ((size_t)b * SEQ + y * 32 + xw) * HIDC + c);
            const bf16* hp = (const bf16*)&hv;
            int wi = (dy + 1) * 3 + (dx + 1);
#pragma unroll
            for (int k = 0; k < 8; k++)
                acc[k] += __bfloat162float(hp[k]) * w[(c + k) * 9 + wi];
        }
    }

    bf16 o[8];
#pragma unroll
    for (int k = 0; k < 8; k++) {
        float gv = 0.5f * acc[k] * (1.0f + erff(acc[k] * 0.70710678118654752f));
        o[k] = __float2bfloat16(gv);
    }
    *(uint4*)(out + ((size_t)b * SEQ + n) * HIDC + c) = *(uint4*)o;
}

// ---------------- launch ----------------------------------------------------
extern "C" void kernel_launch(void* const* d_in, const int* in_sizes, int n_in,
                              void* d_out, int out_size)
{
    const float* x      = (const float*)d_in[0];
    const float* ln1_g  = (const float*)d_in[1];
    const float* ln1_b  = (const float*)d_in[2];
    const float* qkv_w  = (const float*)d_in[3];
    const float* proj_w = (const float*)d_in[4];
    const float* proj_b = (const float*)d_in[5];
    const float* ln2_g  = (const float*)d_in[6];
    const float* ln2_b  = (const float*)d_in[7];
    const float* fc1_w  = (const float*)d_in[8];
    const float* fc1_b  = (const float*)d_in[9];
    const float* dw_w   = (const float*)d_in[10];
    const float* dw_b   = (const float*)d_in[11];
    const float* fc2_w  = (const float*)d_in[12];
    const float* fc2_b  = (const float*)d_in[13];
    float* out = (float*)d_out;

    bf16 *wqkv, *wproj, *wfc1, *wfc2, *ln16, *qkv16, *at16, *h16, *h216;
    float *x1b;
    cudaGetSymbolAddress((void**)&wqkv,  g_wqkv);
    cudaGetSymbolAddress((void**)&wproj, g_wproj);
    cudaGetSymbolAddress((void**)&wfc1,  g_wfc1);
    cudaGetSymbolAddress((void**)&wfc2,  g_wfc2);
    cudaGetSymbolAddress((void**)&ln16,  g_ln16);
    cudaGetSymbolAddress((void**)&qkv16, g_qkv16);
    cudaGetSymbolAddress((void**)&at16,  g_at16);
    cudaGetSymbolAddress((void**)&x1b,   g_x1);
    cudaGetSymbolAddress((void**)&h16,   g_h16);
    cudaGetSymbolAddress((void**)&h216,  g_h216);

    cudaFuncSetAttribute(gemm_bf<float>,
                         cudaFuncAttributeMaxDynamicSharedMemorySize, GT_SMEM);
    cudaFuncSetAttribute(gemm_bf<bf16>,
                         cudaFuncAttributeMaxDynamicSharedMemorySize, GT_SMEM);

    // 0) fused weight conversion (fp32 -> bf16)
    to_bf16_all<<<CVT_TOT/1024, 256>>>(qkv_w, wqkv, proj_w, wproj,
                                       fc1_w, wfc1, fc2_w, wfc2);

    // 1) LN1 -> bf16
    ln_kernel<<<ROWS, 128>>>(x, ln1_g, ln1_b, ln16);

    // 2) QKV GEMM -> bf16
    gemm_bf<bf16><<<dim3(QKVW/128, ROWS/128), 256, GT_SMEM>>>(
        ln16, CH, wqkv, CH, nullptr, nullptr, 0, qkv16, QKVW, CH);

    // 3) flash attention (register-resident) -> bf16
    flash_reg<<<dim3(SEQ/64, BQ*NHD), 128>>>(qkv16, at16);

    // 4) x1 = x + o @ proj_w^T + proj_b   (fp32 out)
    gemm_bf<float><<<dim3(CH/128, ROWS/128), 256, GT_SMEM>>>(
        at16, CH, wproj, CH, proj_b, x, CH, x1b, CH, CH);

    // 5) LN2 -> bf16
    ln_kernel<<<ROWS, 128>>>(x1b, ln2_g, ln2_b, ln16);

    // 6) h = ln2 @ fc1_w^T + fc1_b -> bf16
    gemm_bf<bf16><<<dim3(HIDC/128, ROWS/128), 256, GT_SMEM>>>(
        ln16, CH, wfc1, CH, fc1_b, nullptr, 0, h16, HIDC, CH);

    // 7) depthwise conv + gelu -> bf16 (8 ch/thread)
    dwgelu_kernel<<<dim3(1, SEQ, BQ), 256>>>(h16, dw_w, dw_b, h216);

    // 8) out = x1 + h2 @ fc2_w^T + fc2_b  (fp32 out)
    gemm_bf<float><<<dim3(CH/128, ROWS/128), 256, GT_SMEM>>>(
        h216, HIDC, wfc2, HIDC, fc2_b, x1b, CH, out, CH, HIDC);
}

// round 16
// speedup vs baseline: 1.1202x; 1.1202x over previous
#include <cuda_runtime.h>
#include <cuda_bf16.h>
#include <mma.h>
#include <math.h>
#include <stdint.h>

using namespace nvcuda;
typedef __nv_bfloat16 bf16;

// Problem constants
#define BQ   8
#define SEQ  1024
#define CH   512
#define HIDC 2048
#define NHD  8
#define HDIM 64
#define ROWS (BQ*SEQ)          // 8192
#define QKVW (3*CH)            // 1536

// ---------------- scratch ----------------------------------------------------
__device__ bf16  g_wqkv[QKVW*CH];
__device__ bf16  g_wproj[CH*CH];
__device__ bf16  g_wfc1[HIDC*CH];
__device__ bf16  g_wfc2[CH*HIDC];
__device__ bf16  g_ln16[ROWS*CH];
__device__ bf16  g_qkv16[(size_t)ROWS*QKVW];
__device__ bf16  g_at16[ROWS*CH];
__device__ float g_x1 [ROWS*CH];
__device__ bf16  g_h16 [(size_t)ROWS*HIDC];
__device__ bf16  g_h216[(size_t)ROWS*HIDC];

// ---------------- helpers ---------------------------------------------------
__device__ __forceinline__ uint32_t su32(const void* p) {
    uint32_t a;
    asm("{ .reg .u64 t; cvta.to.shared.u64 t, %1; cvt.u32.u64 %0, t; }"
        : "=r"(a) : "l"(p));
    return a;
}
#define CPA16(d, s) asm volatile("cp.async.cg.shared.global [%0], [%1], 16;" :: "r"(d), "l"(s))
#define CPCOMMIT()  asm volatile("cp.async.commit_group;" ::: "memory")
#define CPWAIT(n)   asm volatile("cp.async.wait_group %0;" :: "n"(n) : "memory")

__device__ __forceinline__ void mma_bf16(float c[4],
    uint32_t a0, uint32_t a1, uint32_t a2, uint32_t a3,
    uint32_t b0, uint32_t b1)
{
    asm volatile(
        "mma.sync.aligned.m16n8k16.row.col.f32.bf16.bf16.f32 "
        "{%0,%1,%2,%3}, {%4,%5,%6,%7}, {%8,%9}, {%0,%1,%2,%3};"
        : "+f"(c[0]), "+f"(c[1]), "+f"(c[2]), "+f"(c[3])
        : "r"(a0), "r"(a1), "r"(a2), "r"(a3), "r"(b0), "r"(b1));
}
__device__ __forceinline__ void ldsm4t(uint32_t r[4], uint32_t addr) {
    asm volatile("ldmatrix.sync.aligned.m8n8.x4.trans.shared.b16 {%0,%1,%2,%3}, [%4];"
                 : "=r"(r[0]), "=r"(r[1]), "=r"(r[2]), "=r"(r[3]) : "r"(addr));
}
__device__ __forceinline__ uint32_t packbf(float lo, float hi) {
    uint32_t r;
    asm("cvt.rn.bf16x2.f32 %0, %1, %2;" : "=r"(r) : "f"(hi), "f"(lo));
    return r;
}

// ---------------- fp32 -> bf16 convert --------------------------------------
__global__ void to_bf16(const float* __restrict__ s, bf16* __restrict__ d)
{
    size_t i = ((size_t)blockIdx.x * 256 + threadIdx.x) * 4;
    float4 v = *(const float4*)(s + i);
    bf16 t[4] = { __float2bfloat16(v.x), __float2bfloat16(v.y),
                  __float2bfloat16(v.z), __float2bfloat16(v.w) };
    *(uint2*)(d + i) = *(uint2*)t;
}

// ---------------- LayerNorm (fp32 in, bf16 out) -----------------------------
__global__ void ln_kernel(const float* __restrict__ x,
                          const float* __restrict__ g,
                          const float* __restrict__ b,
                          bf16* __restrict__ out)
{
    int row = blockIdx.x;
    const float* xr = x + (size_t)row * CH;
    bf16* orow = out + (size_t)row * CH;
    int t = threadIdx.x;
    float v[4];
    float s = 0.f;
#pragma unroll
    for (int i = 0; i < 4; i++) { v[i] = xr[t + i*128]; s += v[i]; }
    __shared__ float red[4];
#pragma unroll
    for (int o = 16; o > 0; o >>= 1) s += __shfl_xor_sync(0xffffffffu, s, o);
    if ((t & 31) == 0) red[t >> 5] = s;
    __syncthreads();
    float mean = (red[0] + red[1] + red[2] + red[3]) * (1.0f / CH);
    float vs = 0.f;
#pragma unroll
    for (int i = 0; i < 4; i++) { float d = v[i] - mean; vs += d * d; }
#pragma unroll
    for (int o = 16; o > 0; o >>= 1) vs += __shfl_xor_sync(0xffffffffu, vs, o);
    __syncthreads();
    if ((t & 31) == 0) red[t >> 5] = vs;
    __syncthreads();
    float var = (red[0] + red[1] + red[2] + red[3]) * (1.0f / CH);
    float rstd = rsqrtf(var + 1e-5f);
#pragma unroll
    for (int i = 0; i < 4; i++) {
        int c = t + i*128;
        orow[c] = __float2bfloat16((v[i] - mean) * rstd * g[c] + b[c]);
    }
}

// ---------------- bf16 WMMA GEMM, 2-stage cp.async (R13 proven) -------------
#define LDSB 72                 // bf16 elems per smem row (144B)
#define TILE_E (128*LDSB)
#define GT_SMEM (4*TILE_E*2)    // 73728

template<typename OutT>
__global__ __launch_bounds__(256, 2)
void gemm_bf(const bf16* __restrict__ A, int lda,
             const bf16* __restrict__ B, int ldb,
             const float* __restrict__ bias,
             const float* __restrict__ res, int ldres,
             OutT* __restrict__ out, int ldo, int K)
{
    extern __shared__ char dsmc[];
    bf16* As = (bf16*)dsmc;
    bf16* Bs = As + 2*TILE_E;

    int tid = threadIdx.x;
    int wid = tid >> 5;
    int wm = wid >> 2;
    int wn = wid & 3;
    int m0 = blockIdx.y * 128;
    int n0 = blockIdx.x * 128;

    wmma::fragment<wmma::accumulator, 16, 16, 16, float> fc[4][2];
#pragma unroll
    for (int i = 0; i < 4; i++)
#pragma unroll
        for (int j = 0; j < 2; j++)
            wmma::fill_fragment(fc[i][j], 0.0f);

    int lrow  = tid >> 1;
    int sbase = (tid & 1) * 4;

    int nK = K / 64;

#pragma unroll
    for (int j = 0; j < 4; j++) {
        int cseg = (sbase + j) * 8;
        CPA16(su32(&As[lrow * LDSB + cseg]), A + (size_t)(m0 + lrow) * lda + cseg);
        CPA16(su32(&Bs[lrow * LDSB + cseg]), B + (size_t)(n0 + lrow) * ldb + cseg);
    }
    CPCOMMIT();

    for (int kc = 0; kc < nK; kc++) {
        int cur = kc & 1;
        if (kc + 1 < nK) {
            int nxt = cur ^ 1;
            int k0 = (kc + 1) * 64;
#pragma unroll
            for (int j = 0; j < 4; j++) {
                int cseg = (sbase + j) * 8;
                CPA16(su32(&As[nxt * TILE_E + lrow * LDSB + cseg]),
                      A + (size_t)(m0 + lrow) * lda + k0 + cseg);
                CPA16(su32(&Bs[nxt * TILE_E + lrow * LDSB + cseg]),
                      B + (size_t)(n0 + lrow) * ldb + k0 + cseg);
            }
            CPCOMMIT();
            CPWAIT(1);
        } else {
            CPWAIT(0);
        }
        __syncthreads();

        bf16* Ac = As + cur * TILE_E;
        bf16* Bc = Bs + cur * TILE_E;
#pragma unroll
        for (int ks = 0; ks < 4; ks++) {
            wmma::fragment<wmma::matrix_a, 16, 16, 16, bf16, wmma::row_major> fa[4];
            wmma::fragment<wmma::matrix_b, 16, 16, 16, bf16, wmma::col_major> fb[2];
#pragma unroll
            for (int i = 0; i < 4; i++)
                wmma::load_matrix_sync(fa[i], &Ac[(wm * 64 + i * 16) * LDSB + ks * 16], LDSB);
#pragma unroll
            for (int j = 0; j < 2; j++)
                wmma::load_matrix_sync(fb[j], &Bc[(wn * 32 + j * 16) * LDSB + ks * 16], LDSB);
#pragma unroll
            for (int i = 0; i < 4; i++)
#pragma unroll
                for (int j = 0; j < 2; j++)
                    wmma::mma_sync(fc[i][j], fa[i], fb[j], fc[i][j]);
        }
        __syncthreads();
    }

    float* eps = (float*)dsmc;
#pragma unroll
    for (int i = 0; i < 4; i++)
#pragma unroll
        for (int j = 0; j < 2; j++)
            wmma::store_matrix_sync(&eps[(wm * 64 + i * 16) * 132 + wn * 32 + j * 16],
                                    fc[i][j], 132, wmma::mem_row_major);
    __syncthreads();

    int r = tid >> 1;
    int c0 = (tid & 1) * 64;
#pragma unroll
    for (int c = 0; c < 64; c += 4) {
        float4 v = *(float4*)&eps[r * 132 + c0 + c];
        int n = n0 + c0 + c;
        if (bias) {
            v.x += bias[n]; v.y += bias[n + 1]; v.z += bias[n + 2]; v.w += bias[n + 3];
        }
        if (res) {
            float4 rr = *(const float4*)(res + (size_t)(m0 + r) * ldres + n);
            v.x += rr.x; v.y += rr.y; v.z += rr.z; v.w += rr.w;
        }
        if constexpr (sizeof(OutT) == 4) {
            *(float4*)((float*)out + (size_t)(m0 + r) * ldo + n) = v;
        } else {
            bf16 t[4] = { __float2bfloat16(v.x), __float2bfloat16(v.y),
                          __float2bfloat16(v.z), __float2bfloat16(v.w) };
            *(uint2*)((bf16*)out + (size_t)(m0 + r) * ldo + n) = *(uint2*)t;
        }
    }
}

// ---------------- Flash attention: 128-query tile, register-resident --------
// CTA: 128 queries x one head; 256 threads (8 warps), warp = 16 query rows.
// K/V tiles (64 keys) double-buffered; each tile serves all 128 queries.
#define FL_SMEM ((128 + 4*64) * LDSB * 2)   // Qs + 2xK + 2xV = 55296 bytes

__global__ __launch_bounds__(256)
void flash_reg(const bf16* __restrict__ qkv, bf16* __restrict__ out)
{
    extern __shared__ char fsc[];
    bf16* Qs  = (bf16*)fsc;                 // [128][LDSB]
    bf16* Kb0 = Qs  + 128 * LDSB;
    bf16* Kb1 = Kb0 + 64 * LDSB;
    bf16* Vb0 = Kb1 + 64 * LDSB;
    bf16* Vb1 = Vb0 + 64 * LDSB;
    bf16* KbA[2] = { Kb0, Kb1 };
    bf16* VbA[2] = { Vb0, Vb1 };

    int bz = blockIdx.y;
    int bI = bz / NHD, hI = bz % NHD;
    int q0 = blockIdx.x * 128;
    const bf16* base = qkv + (size_t)bI * SEQ * QKVW + hI * 3 * HDIM;

    int tid = threadIdx.x;
    int wid = tid >> 5;
    int lane = tid & 31;
    int lr2 = tid >> 2;             // 0..63  (K/V rows)
    int lc2 = (tid & 3) * 16;       // 0,16,32,48
    int lrq = tid >> 1;             // 0..127 (Q rows)
    int lcq = (tid & 1) * 32;

    auto issue_kv = [&](int t0) {
        int buf = (t0 >> 6) & 1;
        const bf16* kp = base + (size_t)(t0 + lr2) * QKVW + HDIM + lc2;
        const bf16* vp = base + (size_t)(t0 + lr2) * QKVW + 2 * HDIM + lc2;
        CPA16(su32(&KbA[buf][lr2 * LDSB + lc2]),     kp);
        CPA16(su32(&KbA[buf][lr2 * LDSB + lc2 + 8]), kp + 8);
        CPA16(su32(&VbA[buf][lr2 * LDSB + lc2]),     vp);
        CPA16(su32(&VbA[buf][lr2 * LDSB + lc2 + 8]), vp + 8);
        CPCOMMIT();
    };

    issue_kv(0);
    // Q -> smem : 32 cols per thread = 4 x uint4
    {
        const bf16* qp = base + (size_t)(q0 + lrq) * QKVW + lcq;
#pragma unroll
        for (int j = 0; j < 4; j++)
            *(uint4*)&Qs[lrq * LDSB + lcq + j * 8] = *(const uint4*)(qp + j * 8);
    }
    __syncthreads();

    // Q A-fragments: warp rows wid*16..+15
    uint32_t qa[4][4];
    {
        int r0 = wid * 16 + (lane >> 2);
        int cb = (lane & 3) * 2;
#pragma unroll
        for (int kb = 0; kb < 4; kb++) {
            const bf16* qb = &Qs[0] + kb * 16 + cb;
            qa[kb][0] = *(const uint32_t*)(qb + (size_t)r0 * LDSB);
            qa[kb][1] = *(const uint32_t*)(qb + (size_t)(r0 + 8) * LDSB);
            qa[kb][2] = *(const uint32_t*)(qb + (size_t)r0 * LDSB + 8);
            qa[kb][3] = *(const uint32_t*)(qb + (size_t)(r0 + 8) * LDSB + 8);
        }
    }

    float oc[8][4];
#pragma unroll
    for (int nt = 0; nt < 8; nt++)
#pragma unroll
        for (int j = 0; j < 4; j++) oc[nt][j] = 0.f;
    float mrow[2] = { -1e30f, -1e30f };
    float lsum[2] = { 0.f, 0.f };

    int krow = lane >> 2;
    int kcol = (lane & 3) * 2;
    int lmrow = (lane & 7) + ((lane >> 3) & 1) * 8;
    int lmcol = (lane >> 4) * 8;

    for (int t0 = 0; t0 < SEQ; t0 += 64) {
        CPWAIT(0);
        __syncthreads();
        if (t0 + 64 < SEQ) issue_kv(t0 + 64);

        int buf = (t0 >> 6) & 1;
        const bf16* Ks = KbA[buf];
        const bf16* Vs = VbA[buf];

        // ---- S = Q @ K^T : 8 n-tiles x 4 k-blocks
        float sc[8][4];
#pragma unroll
        for (int nt = 0; nt < 8; nt++)
#pragma unroll
            for (int j = 0; j < 4; j++) sc[nt][j] = 0.f;
#pragma unroll
        for (int kb = 0; kb < 4; kb++) {
#pragma unroll
            for (int nt = 0; nt < 8; nt++) {
                const bf16* kbp = Ks + (size_t)(nt * 8 + krow) * LDSB + kb * 16 + kcol;
                uint32_t b0 = *(const uint32_t*)(kbp);
                uint32_t b1 = *(const uint32_t*)(kbp + 8);
                mma_bf16(sc[nt], qa[kb][0], qa[kb][1], qa[kb][2], qa[kb][3], b0, b1);
            }
        }

        // ---- online softmax in registers
        float mx0 = -1e30f, mx1 = -1e30f;
#pragma unroll
        for (int nt = 0; nt < 8; nt++) {
            mx0 = fmaxf(mx0, fmaxf(sc[nt][0], sc[nt][1]));
            mx1 = fmaxf(mx1, fmaxf(sc[nt][2], sc[nt][3]));
        }
        mx0 *= 0.125f; mx1 *= 0.125f;
        mx0 = fmaxf(mx0, __shfl_xor_sync(0xffffffffu, mx0, 1));
        mx0 = fmaxf(mx0, __shfl_xor_sync(0xffffffffu, mx0, 2));
        mx1 = fmaxf(mx1, __shfl_xor_sync(0xffffffffu, mx1, 1));
        mx1 = fmaxf(mx1, __shfl_xor_sync(0xffffffffu, mx1, 2));

        float mn0 = fmaxf(mrow[0], mx0);
        float mn1 = fmaxf(mrow[1], mx1);
        float sf0 = __expf(mrow[0] - mn0);
        float sf1 = __expf(mrow[1] - mn1);
        mrow[0] = mn0; mrow[1] = mn1;

        float sum0 = 0.f, sum1 = 0.f;
#pragma unroll
        for (int nt = 0; nt < 8; nt++) {
            sc[nt][0] = __expf(sc[nt][0] * 0.125f - mn0);
            sc[nt][1] = __expf(sc[nt][1] * 0.125f - mn0);
            sc[nt][2] = __expf(sc[nt][2] * 0.125f - mn1);
            sc[nt][3] = __expf(sc[nt][3] * 0.125f - mn1);
            sum0 += sc[nt][0] + sc[nt][1];
            sum1 += sc[nt][2] + sc[nt][3];
        }
        sum0 += __shfl_xor_sync(0xffffffffu, sum0, 1);
        sum0 += __shfl_xor_sync(0xffffffffu, sum0, 2);
        sum1 += __shfl_xor_sync(0xffffffffu, sum1, 1);
        sum1 += __shfl_xor_sync(0xffffffffu, sum1, 2);
        lsum[0] = lsum[0] * sf0 + sum0;
        lsum[1] = lsum[1] * sf1 + sum1;

#pragma unroll
        for (int nt = 0; nt < 8; nt++) {
            oc[nt][0] *= sf0; oc[nt][1] *= sf0;
            oc[nt][2] *= sf1; oc[nt][3] *= sf1;
        }

        // ---- pack P into A-fragments
        uint32_t pa[4][4];
#pragma unroll
        for (int kb = 0; kb < 4; kb++) {
            pa[kb][0] = packbf(sc[2*kb][0],   sc[2*kb][1]);
            pa[kb][1] = packbf(sc[2*kb][2],   sc[2*kb][3]);
            pa[kb][2] = packbf(sc[2*kb+1][0], sc[2*kb+1][1]);
            pa[kb][3] = packbf(sc[2*kb+1][2], sc[2*kb+1][3]);
        }

        // ---- O += P @ V
#pragma unroll
        for (int kb = 0; kb < 4; kb++) {
#pragma unroll
            for (int dg = 0; dg < 4; dg++) {
                uint32_t vr[4];
                uint32_t addr = su32(Vs + (size_t)(kb * 16 + lmrow) * LDSB + dg * 16 + lmcol);
                ldsm4t(vr, addr);
                mma_bf16(oc[2*dg],     pa[kb][0], pa[kb][1], pa[kb][2], pa[kb][3], vr[0], vr[1]);
                mma_bf16(oc[2*dg + 1], pa[kb][0], pa[kb][1], pa[kb][2], pa[kb][3], vr[2], vr[3]);
            }
        }
    }

    // ---- writeout O / l
    {
        float inv0 = 1.0f / lsum[0];
        float inv1 = 1.0f / lsum[1];
        int r0 = wid * 16 + (lane >> 2);
        int cb = (lane & 3) * 2;
        bf16* op0 = out + ((size_t)bI * SEQ + q0 + r0) * CH + hI * HDIM + cb;
        bf16* op1 = op0 + (size_t)8 * CH;
#pragma unroll
        for (int nt = 0; nt < 8; nt++) {
            *(uint32_t*)(op0 + nt * 8) = packbf(oc[nt][0] * inv0, oc[nt][1] * inv0);
            *(uint32_t*)(op1 + nt * 8) = packbf(oc[nt][2] * inv1, oc[nt][3] * inv1);
        }
    }
}

// ---------------- Depthwise 3x3 conv + exact GELU (bf16 io, R13) ------------
__global__ void dwgelu_kernel(const bf16* __restrict__ h,
                              const float* __restrict__ w,
                              const float* __restrict__ bias,
                              bf16* __restrict__ out)
{
    int c = blockIdx.x * 256 + threadIdx.x;
    int n = blockIdx.y;
    int b = blockIdx.z;
    int hh = n >> 5, ww = n & 31;
    float acc = bias[c];
#pragma unroll
    for (int dy = -1; dy <= 1; dy++) {
        int y = hh + dy;
        if (y < 0 || y >= 32) continue;
#pragma unroll
        for (int dx = -1; dx <= 1; dx++) {
            int xw = ww + dx;
            if (xw < 0 || xw >= 32) continue;
            acc += __bfloat162float(h[((size_t)b * SEQ + y * 32 + xw) * HIDC + c])
                 * w[c * 9 + (dy + 1) * 3 + (dx + 1)];
        }
    }
    float gv = 0.5f * acc * (1.0f + erff(acc * 0.70710678118654752f));
    out[((size_t)b * SEQ + n) * HIDC + c] = __float2bfloat16(gv);
}

// ---------------- launch ----------------------------------------------------
extern "C" void kernel_launch(void* const* d_in, const int* in_sizes, int n_in,
                              void* d_out, int out_size)
{
    const float* x      = (const float*)d_in[0];
    const float* ln1_g  = (const float*)d_in[1];
    const float* ln1_b  = (const float*)d_in[2];
    const float* qkv_w  = (const float*)d_in[3];
    const float* proj_w = (const float*)d_in[4];
    const float* proj_b = (const float*)d_in[5];
    const float* ln2_g  = (const float*)d_in[6];
    const float* ln2_b  = (const float*)d_in[7];
    const float* fc1_w  = (const float*)d_in[8];
    const float* fc1_b  = (const float*)d_in[9];
    const float* dw_w   = (const float*)d_in[10];
    const float* dw_b   = (const float*)d_in[11];
    const float* fc2_w  = (const float*)d_in[12];
    const float* fc2_b  = (const float*)d_in[13];
    float* out = (float*)d_out;

    bf16 *wqkv, *wproj, *wfc1, *wfc2, *ln16, *qkv16, *at16, *h16, *h216;
    float *x1b;
    cudaGetSymbolAddress((void**)&wqkv,  g_wqkv);
    cudaGetSymbolAddress((void**)&wproj, g_wproj);
    cudaGetSymbolAddress((void**)&wfc1,  g_wfc1);
    cudaGetSymbolAddress((void**)&wfc2,  g_wfc2);
    cudaGetSymbolAddress((void**)&ln16,  g_ln16);
    cudaGetSymbolAddress((void**)&qkv16, g_qkv16);
    cudaGetSymbolAddress((void**)&at16,  g_at16);
    cudaGetSymbolAddress((void**)&x1b,   g_x1);
    cudaGetSymbolAddress((void**)&h16,   g_h16);
    cudaGetSymbolAddress((void**)&h216,  g_h216);

    cudaFuncSetAttribute(gemm_bf<float>,
                         cudaFuncAttributeMaxDynamicSharedMemorySize, GT_SMEM);
    cudaFuncSetAttribute(gemm_bf<bf16>,
                         cudaFuncAttributeMaxDynamicSharedMemorySize, GT_SMEM);
    cudaFuncSetAttribute(flash_reg,
                         cudaFuncAttributeMaxDynamicSharedMemorySize, FL_SMEM);

    // 0) weight conversion (fp32 -> bf16)
    to_bf16<<<(QKVW*CH)/1024, 256>>>(qkv_w,  wqkv);
    to_bf16<<<(CH*CH)/1024,   256>>>(proj_w, wproj);
    to_bf16<<<(HIDC*CH)/1024, 256>>>(fc1_w,  wfc1);
    to_bf16<<<(CH*HIDC)/1024, 256>>>(fc2_w,  wfc2);

    // 1) LN1 -> bf16
    ln_kernel<<<ROWS, 128>>>(x, ln1_g, ln1_b, ln16);

    // 2) QKV GEMM -> bf16
    gemm_bf<bf16><<<dim3(QKVW/128, ROWS/128), 256, GT_SMEM>>>(
        ln16, CH, wqkv, CH, nullptr, nullptr, 0, qkv16, QKVW, CH);

    // 3) flash attention (128-query tiles) -> bf16
    flash_reg<<<dim3(SEQ/128, BQ*NHD), 256, FL_SMEM>>>(qkv16, at16);

    // 4) x1 = x + o @ proj_w^T + proj_b   (fp32 out)
    gemm_bf<float><<<dim3(CH/128, ROWS/128), 256, GT_SMEM>>>(
        at16, CH, wproj, CH, proj_b, x, CH, x1b, CH, CH);

    // 5) LN2 -> bf16
    ln_kernel<<<ROWS, 128>>>(x1b, ln2_g, ln2_b, ln16);

    // 6) h = ln2 @ fc1_w^T + fc1_b -> bf16
    gemm_bf<bf16><<<dim3(HIDC/128, ROWS/128), 256, GT_SMEM>>>(
        ln16, CH, wfc1, CH, fc1_b, nullptr, 0, h16, HIDC, CH);

    // 7) depthwise conv + gelu -> bf16
    dwgelu_kernel<<<dim3(HIDC/256, SEQ, BQ), 256>>>(h16, dw_w, dw_b, h216);

    // 8) out = x1 + h2 @ fc2_w^T + fc2_b  (fp32 out)
    gemm_bf<float><<<dim3(CH/128, ROWS/128), 256, GT_SMEM>>>(
        h216, HIDC, wfc2, HIDC, fc2_b, x1b, CH, out, CH, HIDC);
}